// round 6
// baseline (speedup 1.0000x reference)
#include <cuda_runtime.h>

// Problem shape (fixed by setup_inputs):
//   x1: [B=32, C=64, h=42, w=42]       float32
//   x2: [B=32, S=25, C=64, h=42, w=42] float32
//   out: [B, S*h*w] = [32, 44100]      float32
// out[b, s*HW + p] = sqrt( sum_c (x1[b,c,p] - x2[b,s,c,p])^2 )

#define B_   32
#define S_   25
#define C_   64
#define HW_  1764          // 42*42
#define HW4_ 441           // HW/4 (exact)

#define SG_  5             // supports per thread
#define NSG_ (S_ / SG_)    // 5 support-groups
#define TOTAL_ (B_ * NSG_ * HW4_)   // 70560 threads

#define PLANE4_ (C_ * HW4_)         // float4s per [C,h,w] slab = 28224

#define BLOCK_ 128

__global__ __launch_bounds__(BLOCK_, 4)
void euclidean_block_kernel(const float* __restrict__ x1,
                            const float* __restrict__ x2,
                            float* __restrict__ out) {
    int t = blockIdx.x * BLOCK_ + threadIdx.x;
    if (t >= TOTAL_) return;

    int p4   = t % HW4_;
    int rest = t / HW4_;
    int sg   = rest % NSG_;
    int b    = rest / NSG_;

    const float4* __restrict__ x1p =
        reinterpret_cast<const float4*>(x1) + (size_t)b * PLANE4_ + p4;
    const float4* __restrict__ x2p =
        reinterpret_cast<const float4*>(x2) +
        ((size_t)b * S_ + sg * SG_) * PLANE4_ + p4;

    float4 acc[SG_];
    #pragma unroll
    for (int j = 0; j < SG_; ++j) acc[j] = make_float4(0.f, 0.f, 0.f, 0.f);

    // Double-buffered register pipeline over channels:
    // per channel: 1 x1 load + 5 x2 loads, consumed one stage behind.
    float4 a0, a1, v0[SG_], v1[SG_];

    a0 = x1p[0];
    #pragma unroll
    for (int j = 0; j < SG_; ++j) v0[j] = __ldcs(&x2p[(size_t)j * PLANE4_]);

    #pragma unroll 4
    for (int c = 0; c < C_ - 2; c += 2) {
        a1 = x1p[(c + 1) * HW4_];
        #pragma unroll
        for (int j = 0; j < SG_; ++j)
            v1[j] = __ldcs(&x2p[(size_t)j * PLANE4_ + (c + 1) * HW4_]);

        #pragma unroll
        for (int j = 0; j < SG_; ++j) {
            float d0 = a0.x - v0[j].x;
            float d1 = a0.y - v0[j].y;
            float d2 = a0.z - v0[j].z;
            float d3 = a0.w - v0[j].w;
            acc[j].x = fmaf(d0, d0, acc[j].x);
            acc[j].y = fmaf(d1, d1, acc[j].y);
            acc[j].z = fmaf(d2, d2, acc[j].z);
            acc[j].w = fmaf(d3, d3, acc[j].w);
        }

        a0 = x1p[(c + 2) * HW4_];
        #pragma unroll
        for (int j = 0; j < SG_; ++j)
            v0[j] = __ldcs(&x2p[(size_t)j * PLANE4_ + (c + 2) * HW4_]);

        #pragma unroll
        for (int j = 0; j < SG_; ++j) {
            float d0 = a1.x - v1[j].x;
            float d1 = a1.y - v1[j].y;
            float d2 = a1.z - v1[j].z;
            float d3 = a1.w - v1[j].w;
            acc[j].x = fmaf(d0, d0, acc[j].x);
            acc[j].y = fmaf(d1, d1, acc[j].y);
            acc[j].z = fmaf(d2, d2, acc[j].z);
            acc[j].w = fmaf(d3, d3, acc[j].w);
        }
    }

    // epilogue: buffer 0 holds channel 62; load+consume channel 63
    a1 = x1p[(C_ - 1) * HW4_];
    #pragma unroll
    for (int j = 0; j < SG_; ++j)
        v1[j] = __ldcs(&x2p[(size_t)j * PLANE4_ + (C_ - 1) * HW4_]);

    #pragma unroll
    for (int j = 0; j < SG_; ++j) {
        float d0 = a0.x - v0[j].x;
        float d1 = a0.y - v0[j].y;
        float d2 = a0.z - v0[j].z;
        float d3 = a0.w - v0[j].w;
        acc[j].x = fmaf(d0, d0, acc[j].x);
        acc[j].y = fmaf(d1, d1, acc[j].y);
        acc[j].z = fmaf(d2, d2, acc[j].z);
        acc[j].w = fmaf(d3, d3, acc[j].w);
    }
    #pragma unroll
    for (int j = 0; j < SG_; ++j) {
        float d0 = a1.x - v1[j].x;
        float d1 = a1.y - v1[j].y;
        float d2 = a1.z - v1[j].z;
        float d3 = a1.w - v1[j].w;
        acc[j].x = fmaf(d0, d0, acc[j].x);
        acc[j].y = fmaf(d1, d1, acc[j].y);
        acc[j].z = fmaf(d2, d2, acc[j].z);
        acc[j].w = fmaf(d3, d3, acc[j].w);
    }

    // write 5 outputs: (b*25 + sg*5 + j)*441 + p4  (float4 units), streaming
    float4* __restrict__ op =
        reinterpret_cast<float4*>(out) +
        ((size_t)b * S_ + sg * SG_) * HW4_ + p4;
    #pragma unroll
    for (int j = 0; j < SG_; ++j) {
        float4 r;
        r.x = sqrtf(acc[j].x);
        r.y = sqrtf(acc[j].y);
        r.z = sqrtf(acc[j].z);
        r.w = sqrtf(acc[j].w);
        __stcs(&op[(size_t)j * HW4_], r);
    }
}

extern "C" void kernel_launch(void* const* d_in, const int* in_sizes, int n_in,
                              void* d_out, int out_size) {
    const float* x1 = (const float*)d_in[0];
    const float* x2 = (const float*)d_in[1];
    float* out = (float*)d_out;

    const int blocks = (TOTAL_ + BLOCK_ - 1) / BLOCK_;  // 552
    euclidean_block_kernel<<<blocks, BLOCK_>>>(x1, x2, out);
}

// round 7
// speedup vs baseline: 1.0106x; 1.0106x over previous
#include <cuda_runtime.h>

// Problem shape (fixed by setup_inputs):
//   x1: [B=32, C=64, h=42, w=42]       float32
//   x2: [B=32, S=25, C=64, h=42, w=42] float32
//   out: [B, S*h*w] = [32, 44100]      float32
// out[b, s*HW + p] = sqrt( sum_c (x1[b,c,p] - x2[b,s,c,p])^2 )
//
// Linear-stream mapping: one CTA per (b,s) slab. 441 active threads cover one
// full channel plane of float4s, so the channel loop walks the 451KB slab in
// strictly ascending addresses (one contiguous 7056B block per channel).

#define B_   32
#define S_   25
#define C_   64
#define HW_  1764          // 42*42
#define HW4_ 441           // HW/4 (exact) = one channel plane in float4s

#define PLANE4_ (C_ * HW4_)   // float4s per [C,h,w] slab = 28224

#define BLOCK_ 448            // 14 warps; threads 441..447 idle

__global__ __launch_bounds__(BLOCK_, 2)
void euclidean_block_kernel(const float* __restrict__ x1,
                            const float* __restrict__ x2,
                            float* __restrict__ out) {
    const int p4 = threadIdx.x;
    if (p4 >= HW4_) return;

    const int bs = blockIdx.x;       // b*S + s
    const int b  = bs / S_;

    const float4* __restrict__ x1p =
        reinterpret_cast<const float4*>(x1) + (size_t)b * PLANE4_ + p4;
    const float4* __restrict__ x2p =
        reinterpret_cast<const float4*>(x2) + (size_t)bs * PLANE4_ + p4;

    float ax = 0.f, ay = 0.f, az = 0.f, aw = 0.f;

    // Double-buffered pipeline, 2 channels per stage.
    float4 a0[2], v0[2], a1[2], v1[2];

    // prologue: channels 0,1 -> buffer 0
    #pragma unroll
    for (int i = 0; i < 2; ++i) {
        a0[i] = x1p[i * HW4_];
        v0[i] = __ldcs(&x2p[i * HW4_]);
    }

    #pragma unroll 5
    for (int c = 0; c < C_ - 4; c += 4) {
        // load channels c+2,c+3 -> buffer 1
        #pragma unroll
        for (int i = 0; i < 2; ++i) {
            a1[i] = x1p[(c + 2 + i) * HW4_];
            v1[i] = __ldcs(&x2p[(c + 2 + i) * HW4_]);
        }
        // consume channels c,c+1 (buffer 0)
        #pragma unroll
        for (int i = 0; i < 2; ++i) {
            float d0 = a0[i].x - v0[i].x;
            float d1 = a0[i].y - v0[i].y;
            float d2 = a0[i].z - v0[i].z;
            float d3 = a0[i].w - v0[i].w;
            ax = fmaf(d0, d0, ax);
            ay = fmaf(d1, d1, ay);
            az = fmaf(d2, d2, az);
            aw = fmaf(d3, d3, aw);
        }
        // load channels c+4,c+5 -> buffer 0
        #pragma unroll
        for (int i = 0; i < 2; ++i) {
            a0[i] = x1p[(c + 4 + i) * HW4_];
            v0[i] = __ldcs(&x2p[(c + 4 + i) * HW4_]);
        }
        // consume channels c+2,c+3 (buffer 1)
        #pragma unroll
        for (int i = 0; i < 2; ++i) {
            float d0 = a1[i].x - v1[i].x;
            float d1 = a1[i].y - v1[i].y;
            float d2 = a1[i].z - v1[i].z;
            float d3 = a1[i].w - v1[i].w;
            ax = fmaf(d0, d0, ax);
            ay = fmaf(d1, d1, ay);
            az = fmaf(d2, d2, az);
            aw = fmaf(d3, d3, aw);
        }
    }

    // epilogue: buffer 0 holds channels 60,61; load+consume 62,63
    #pragma unroll
    for (int i = 0; i < 2; ++i) {
        a1[i] = x1p[(C_ - 2 + i) * HW4_];
        v1[i] = __ldcs(&x2p[(C_ - 2 + i) * HW4_]);
    }
    #pragma unroll
    for (int i = 0; i < 2; ++i) {
        float d0 = a0[i].x - v0[i].x;
        float d1 = a0[i].y - v0[i].y;
        float d2 = a0[i].z - v0[i].z;
        float d3 = a0[i].w - v0[i].w;
        ax = fmaf(d0, d0, ax);
        ay = fmaf(d1, d1, ay);
        az = fmaf(d2, d2, az);
        aw = fmaf(d3, d3, aw);
    }
    #pragma unroll
    for (int i = 0; i < 2; ++i) {
        float d0 = a1[i].x - v1[i].x;
        float d1 = a1[i].y - v1[i].y;
        float d2 = a1[i].z - v1[i].z;
        float d3 = a1[i].w - v1[i].w;
        ax = fmaf(d0, d0, ax);
        ay = fmaf(d1, d1, ay);
        az = fmaf(d2, d2, az);
        aw = fmaf(d3, d3, aw);
    }

    float4 r;
    r.x = sqrtf(ax);
    r.y = sqrtf(ay);
    r.z = sqrtf(az);
    r.w = sqrtf(aw);
    __stcs(&reinterpret_cast<float4*>(out)[(size_t)bs * HW4_ + p4], r);
}

extern "C" void kernel_launch(void* const* d_in, const int* in_sizes, int n_in,
                              void* d_out, int out_size) {
    const float* x1 = (const float*)d_in[0];
    const float* x2 = (const float*)d_in[1];
    float* out = (float*)d_out;

    euclidean_block_kernel<<<B_ * S_, BLOCK_>>>(x1, x2, out);  // 800 CTAs
}